// round 1
// baseline (speedup 1.0000x reference)
#include <cuda_runtime.h>

// MSELoss: out = mean((yhat - y)^2) over 16384 x 4096 fp32.
// Pure HBM-streaming reduction. float4 loads, warp-shuffle + shared reduce,
// one atomicAdd per block of pre-scaled partial.

#define BLOCK 256

__global__ void mse_kernel(const float4* __restrict__ yhat,
                           const float4* __restrict__ y,
                           float* __restrict__ out,
                           int n4, float inv_n) {
    float acc = 0.0f;
    int stride = gridDim.x * blockDim.x;
    for (int i = blockIdx.x * blockDim.x + threadIdx.x; i < n4; i += stride) {
        float4 a = __ldg(&yhat[i]);
        float4 b = __ldg(&y[i]);
        float d0 = a.x - b.x;
        float d1 = a.y - b.y;
        float d2 = a.z - b.z;
        float d3 = a.w - b.w;
        acc = fmaf(d0, d0, acc);
        acc = fmaf(d1, d1, acc);
        acc = fmaf(d2, d2, acc);
        acc = fmaf(d3, d3, acc);
    }

    // warp reduce
    #pragma unroll
    for (int off = 16; off > 0; off >>= 1)
        acc += __shfl_xor_sync(0xFFFFFFFFu, acc, off);

    __shared__ float warp_sums[BLOCK / 32];
    int lane = threadIdx.x & 31;
    int wid  = threadIdx.x >> 5;
    if (lane == 0) warp_sums[wid] = acc;
    __syncthreads();

    if (wid == 0) {
        float v = (lane < BLOCK / 32) ? warp_sums[lane] : 0.0f;
        #pragma unroll
        for (int off = 16; off > 0; off >>= 1)
            v += __shfl_xor_sync(0xFFFFFFFFu, v, off);
        if (lane == 0)
            atomicAdd(out, v * inv_n);
    }
}

extern "C" void kernel_launch(void* const* d_in, const int* in_sizes, int n_in,
                              void* d_out, int out_size) {
    const float4* yhat = (const float4*)d_in[0];
    const float4* y    = (const float4*)d_in[1];
    float* out = (float*)d_out;

    long long n = (long long)in_sizes[0];       // 16384*4096 = 67108864
    int n4 = (int)(n / 4);                      // 16777216 float4 per input
    float inv_n = 1.0f / (float)n;

    cudaMemsetAsync(out, 0, sizeof(float));

    int grid = 148 * 16;  // 2368 blocks, grid-stride
    mse_kernel<<<grid, BLOCK>>>(yhat, y, out, n4, inv_n);
}